// round 1
// baseline (speedup 1.0000x reference)
#include <cuda_runtime.h>
#include <math.h>

// Problem constants
#define Bq   8
#define Sq   1024
#define Dq   512
#define Hq   8
#define DHq  64
#define BSr  (Bq*Sq)        // 8192 rows
#define BSD  (Bq*Sq*Dq)     // 4194304 elements

// ---------------- device scratch (no allocations allowed) ----------------
__device__ float g_E [BSD];  // enc_in
__device__ float g_DI[BSD];  // dec_in
__device__ float g_Q [BSD];
__device__ float g_K [BSD];
__device__ float g_V [BSD];
__device__ float g_S [BSD];  // attention output
__device__ float g_I [BSD];  // inter / i2
__device__ float g_EO[BSD];  // enc_out

// ---------------- positional-embedding add ----------------
// pe(s,d) = sin/cos( s / 10000^(2d/512) ), even d -> sin, odd d -> cos
__global__ void __launch_bounds__(256) add_pos_kernel(const float* __restrict__ x,
                                                      float* __restrict__ out) {
    int idx = blockIdx.x * 256 + threadIdx.x;
    int d = idx & (Dq - 1);
    int s = (idx >> 9) & (Sq - 1);
    // exponent = -(2d/512)*ln(10000) = -d * 0.0359778920794f
    float freq  = expf((float)d * -0.0359778920794f);
    float angle = (float)s * freq;
    float pe = (d & 1) ? cosf(angle) : sinf(angle);
    out[idx] = x[idx] + pe;
}

// ---------------- fused LayerNorm + residual ----------------
// out = base + scale * ( (x-mu)*rsqrt(var+eps)*gamma + beta ), row length 512
__global__ void __launch_bounds__(256) ln_add_kernel(const float* __restrict__ x,
                                                     const float* __restrict__ gamma,
                                                     const float* __restrict__ beta,
                                                     const float* __restrict__ basep,
                                                     float scale,
                                                     float* __restrict__ out) {
    __shared__ float red[256];
    int t = threadIdx.x;
    size_t off = (size_t)blockIdx.x * Dq;

    float v0 = x[off + t];
    float v1 = x[off + t + 256];

    red[t] = v0 + v1;
    __syncthreads();
    #pragma unroll
    for (int s2 = 128; s2 > 0; s2 >>= 1) {
        if (t < s2) red[t] += red[t + s2];
        __syncthreads();
    }
    float mu = red[0] * (1.0f / 512.0f);
    __syncthreads();

    float d0 = v0 - mu, d1 = v1 - mu;
    red[t] = d0 * d0 + d1 * d1;
    __syncthreads();
    #pragma unroll
    for (int s2 = 128; s2 > 0; s2 >>= 1) {
        if (t < s2) red[t] += red[t + s2];
        __syncthreads();
    }
    float var = red[0] * (1.0f / 512.0f);
    float rs  = rsqrtf(var + 1e-3f);

    out[off + t]       = basep[off + t]       + scale * (d0 * rs * gamma[t]       + beta[t]);
    out[off + t + 256] = basep[off + t + 256] + scale * (d1 * rs * gamma[t + 256] + beta[t + 256]);
}

// ---------------- SGEMM: C[8192,512] = A[8192,512] @ W[512,512] (+ addend) ----------------
#define GBM 128
#define GBN 64
#define GBK 16
__global__ void __launch_bounds__(256) sgemm_kernel(const float* __restrict__ A,
                                                    const float* __restrict__ W,
                                                    const float* __restrict__ addend,
                                                    float* __restrict__ C) {
    __shared__ __align__(16) float As[GBK][GBM + 4]; // stored transposed: As[k][m]
    __shared__ __align__(16) float Bs[GBK][GBN];

    int tid = threadIdx.x;
    int tx = tid & 15;       // n dir, 4 cols each
    int ty = tid >> 4;       // m dir, 4+4 rows each
    int m0 = blockIdx.y * GBM;
    int n0 = blockIdx.x * GBN;

    const float* Ap = A + (size_t)m0 * Dq;
    const float* Wp = W + n0;

    float acc[8][4];
    #pragma unroll
    for (int u = 0; u < 8; u++)
        #pragma unroll
        for (int v = 0; v < 4; v++) acc[u][v] = 0.0f;

    for (int kt = 0; kt < Dq; kt += GBK) {
        // Load A tile 128x16 (transpose into As[k][m])
        #pragma unroll
        for (int p = 0; p < 8; p++) {
            int e = tid + p * 256;
            int r = e >> 4, c = e & 15;
            As[c][r] = Ap[r * Dq + kt + c];
        }
        // Load W tile 16x64
        #pragma unroll
        for (int p = 0; p < 4; p++) {
            int e = tid + p * 256;
            int r = e >> 6, c = e & 63;
            Bs[r][c] = Wp[(size_t)(kt + r) * Dq + c];
        }
        __syncthreads();

        #pragma unroll
        for (int k = 0; k < GBK; k++) {
            float4 a0 = *(const float4*)&As[k][ty * 4];
            float4 a1 = *(const float4*)&As[k][64 + ty * 4];
            float4 b  = *(const float4*)&Bs[k][tx * 4];
            float av[8] = {a0.x, a0.y, a0.z, a0.w, a1.x, a1.y, a1.z, a1.w};
            float bv[4] = {b.x, b.y, b.z, b.w};
            #pragma unroll
            for (int u = 0; u < 8; u++)
                #pragma unroll
                for (int v = 0; v < 4; v++)
                    acc[u][v] += av[u] * bv[v];
        }
        __syncthreads();
    }

    // Epilogue (optional residual add), float4 stores
    #pragma unroll
    for (int u = 0; u < 8; u++) {
        int gm = m0 + ty * 4 + (u & 3) + ((u >> 2) * 64);
        size_t o = (size_t)gm * Dq + n0 + tx * 4;
        float4 r;
        r.x = acc[u][0]; r.y = acc[u][1]; r.z = acc[u][2]; r.w = acc[u][3];
        if (addend) {
            float4 ad = *(const float4*)&addend[o];
            r.x += ad.x; r.y += ad.y; r.z += ad.z; r.w += ad.w;
        }
        *(float4*)&C[o] = r;
    }
}

// ---------------- Flash attention (scale = 1/H, not 1/sqrt(dh)) ----------------
// Per CTA: 64 queries x one head. 256 threads = 16x16, each owns 4x4 of 64x64 tiles.
// smem: Qs[64][64], Vs[64][64], KtP[64][68] (K transposed, then reused for P), alphas[64]
#define FS_FLOATS (4096 + 4096 + 64*68 + 64)   // 12608 floats
#define FS_BYTES  (FS_FLOATS * 4)              // 50432 bytes

__global__ void __launch_bounds__(256) flash_kernel(const float* __restrict__ Q,
                                                    const float* __restrict__ K,
                                                    const float* __restrict__ V,
                                                    float* __restrict__ O) {
    extern __shared__ float sm[];
    float* Qs     = sm;               // [r*64 + c]
    float* Vs     = sm + 4096;        // [r*64 + c]
    float* KtP    = sm + 8192;        // Kt: [c*68 + r], later P: [i*68 + kk]
    float* alphas = sm + 8192 + 64 * 68;

    int tid = threadIdx.x;
    int tx = tid & 15, ty = tid >> 4;
    int i0 = ty * 4, j0 = tx * 4;
    int qb = blockIdx.x, h = blockIdx.y, b = blockIdx.z;

    const size_t baseQ  = ((size_t)b * Sq + (size_t)qb * 64) * Dq + h * DHq;
    const size_t baseKV = ((size_t)b * Sq) * Dq + h * DHq;

    // Load Q tile (64x64), coalesced
    #pragma unroll
    for (int p = 0; p < 16; p++) {
        int e = tid + p * 256;
        int r = e >> 6, c = e & 63;
        Qs[r * 64 + c] = Q[baseQ + (size_t)r * Dq + c];
    }

    float o[4][4];
    #pragma unroll
    for (int u = 0; u < 4; u++)
        #pragma unroll
        for (int v = 0; v < 4; v++) o[u][v] = 0.0f;

    float m_t = -1e30f, l_t = 0.0f;   // live only in threads tid<64 (row = tid)

    for (int kb = 0; kb < Sq / 64; kb++) {
        __syncthreads();  // protect KtP/Vs (prev iter) + orders Q load on first iter

        const float* Kp = K + baseKV + (size_t)kb * 64 * Dq;
        const float* Vp = V + baseKV + (size_t)kb * 64 * Dq;
        #pragma unroll
        for (int p = 0; p < 16; p++) {
            int e = tid + p * 256;
            int r = e >> 6, c = e & 63;
            KtP[c * 68 + r] = Kp[(size_t)r * Dq + c];  // transposed store
            Vs[r * 64 + c]  = Vp[(size_t)r * Dq + c];
        }
        __syncthreads();

        // S = Q @ K^T  (64x64, each thread 4x4)
        float s[4][4];
        #pragma unroll
        for (int u = 0; u < 4; u++)
            #pragma unroll
            for (int v = 0; v < 4; v++) s[u][v] = 0.0f;

        #pragma unroll
        for (int c = 0; c < 64; c += 4) {
            float4 q0 = *(const float4*)&Qs[(i0 + 0) * 64 + c];
            float4 q1 = *(const float4*)&Qs[(i0 + 1) * 64 + c];
            float4 q2 = *(const float4*)&Qs[(i0 + 2) * 64 + c];
            float4 q3 = *(const float4*)&Qs[(i0 + 3) * 64 + c];
            float4 k0 = *(const float4*)&KtP[(c + 0) * 68 + j0];
            float4 k1 = *(const float4*)&KtP[(c + 1) * 68 + j0];
            float4 k2 = *(const float4*)&KtP[(c + 2) * 68 + j0];
            float4 k3 = *(const float4*)&KtP[(c + 3) * 68 + j0];
            #define QKROW(u, qv)                                              \
                s[u][0] += qv.x*k0.x + qv.y*k1.x + qv.z*k2.x + qv.w*k3.x;     \
                s[u][1] += qv.x*k0.y + qv.y*k1.y + qv.z*k2.y + qv.w*k3.y;     \
                s[u][2] += qv.x*k0.z + qv.y*k1.z + qv.z*k2.z + qv.w*k3.z;     \
                s[u][3] += qv.x*k0.w + qv.y*k1.w + qv.z*k2.w + qv.w*k3.w;
            QKROW(0, q0) QKROW(1, q1) QKROW(2, q2) QKROW(3, q3)
            #undef QKROW
        }
        __syncthreads();  // done reading Kt

        // Store P (pre-softmax scores * 1/H) over Kt region
        #pragma unroll
        for (int u = 0; u < 4; u++) {
            float4 pv;
            pv.x = s[u][0] * 0.125f; pv.y = s[u][1] * 0.125f;
            pv.z = s[u][2] * 0.125f; pv.w = s[u][3] * 0.125f;
            *(float4*)&KtP[(i0 + u) * 68 + j0] = pv;
        }
        __syncthreads();

        // Online softmax, one thread per row
        if (tid < 64) {
            float* row = &KtP[tid * 68];
            float mx = row[0];
            #pragma unroll 8
            for (int j = 1; j < 64; j++) mx = fmaxf(mx, row[j]);
            float mnew  = fmaxf(m_t, mx);
            float alpha = __expf(m_t - mnew);
            float sum = 0.0f;
            #pragma unroll 8
            for (int j = 0; j < 64; j++) {
                float p = __expf(row[j] - mnew);
                row[j] = p;
                sum += p;
            }
            l_t = l_t * alpha + sum;
            m_t = mnew;
            alphas[tid] = alpha;
        }
        __syncthreads();

        // Rescale running O, then O += P @ V
        float a0 = alphas[i0 + 0], a1 = alphas[i0 + 1];
        float a2 = alphas[i0 + 2], a3 = alphas[i0 + 3];
        #pragma unroll
        for (int v = 0; v < 4; v++) {
            o[0][v] *= a0; o[1][v] *= a1; o[2][v] *= a2; o[3][v] *= a3;
        }
        #pragma unroll
        for (int kk = 0; kk < 64; kk += 4) {
            float4 p0 = *(const float4*)&KtP[(i0 + 0) * 68 + kk];
            float4 p1 = *(const float4*)&KtP[(i0 + 1) * 68 + kk];
            float4 p2 = *(const float4*)&KtP[(i0 + 2) * 68 + kk];
            float4 p3 = *(const float4*)&KtP[(i0 + 3) * 68 + kk];
            float4 v0 = *(const float4*)&Vs[(kk + 0) * 64 + j0];
            float4 v1 = *(const float4*)&Vs[(kk + 1) * 64 + j0];
            float4 v2 = *(const float4*)&Vs[(kk + 2) * 64 + j0];
            float4 v3 = *(const float4*)&Vs[(kk + 3) * 64 + j0];
            #define PVROW(u, pv)                                              \
                o[u][0] += pv.x*v0.x + pv.y*v1.x + pv.z*v2.x + pv.w*v3.x;     \
                o[u][1] += pv.x*v0.y + pv.y*v1.y + pv.z*v2.y + pv.w*v3.y;     \
                o[u][2] += pv.x*v0.z + pv.y*v1.z + pv.z*v2.z + pv.w*v3.z;     \
                o[u][3] += pv.x*v0.w + pv.y*v1.w + pv.z*v2.w + pv.w*v3.w;
            PVROW(0, p0) PVROW(1, p1) PVROW(2, p2) PVROW(3, p3)
            #undef PVROW
        }
    }

    __syncthreads();
    if (tid < 64) alphas[tid] = 1.0f / l_t;   // reuse alphas as 1/l
    __syncthreads();

    #pragma unroll
    for (int u = 0; u < 4; u++) {
        float li = alphas[i0 + u];
        float4 r;
        r.x = o[u][0] * li; r.y = o[u][1] * li;
        r.z = o[u][2] * li; r.w = o[u][3] * li;
        *(float4*)&O[baseQ + (size_t)(i0 + u) * Dq + j0] = r;
    }
}

// ---------------- launcher ----------------
extern "C" void kernel_launch(void* const* d_in, const int* in_sizes, int n_in,
                              void* d_out, int out_size) {
    const float* in0   = (const float*)d_in[0];   // padded_encoded_input_docs
    const float* in1   = (const float*)d_in[1];   // padded_encoded_output_docs
    const float* Wq_e  = (const float*)d_in[2];
    const float* Wk_e  = (const float*)d_in[3];
    const float* Wv_e  = (const float*)d_in[4];
    const float* Wff_e = (const float*)d_in[5];
    const float* ge    = (const float*)d_in[6];
    const float* be    = (const float*)d_in[7];
    const float* Wq_d  = (const float*)d_in[8];
    const float* Wk_d  = (const float*)d_in[9];
    const float* Wv_d  = (const float*)d_in[10];
    const float* Wff_d = (const float*)d_in[11];
    const float* gd    = (const float*)d_in[12];
    const float* bd    = (const float*)d_in[13];
    float* out = (float*)d_out;

    float *E, *DI, *Qb, *Kb, *Vb, *Sb, *I, *EO;
    cudaGetSymbolAddress((void**)&E,  g_E);
    cudaGetSymbolAddress((void**)&DI, g_DI);
    cudaGetSymbolAddress((void**)&Qb, g_Q);
    cudaGetSymbolAddress((void**)&Kb, g_K);
    cudaGetSymbolAddress((void**)&Vb, g_V);
    cudaGetSymbolAddress((void**)&Sb, g_S);
    cudaGetSymbolAddress((void**)&I,  g_I);
    cudaGetSymbolAddress((void**)&EO, g_EO);

    cudaFuncSetAttribute(flash_kernel, cudaFuncAttributeMaxDynamicSharedMemorySize, FS_BYTES);

    dim3 ggrid(Dq / GBN, BSr / GBM);      // (8, 64)
    dim3 fgrid(Sq / 64, Hq, Bq);          // (16, 8, 8)

    // ---- Encoder ----
    add_pos_kernel<<<BSD / 256, 256>>>(in0, E);                       // enc_in
    sgemm_kernel<<<ggrid, 256>>>(E, Wq_e, nullptr, Qb);
    sgemm_kernel<<<ggrid, 256>>>(E, Wk_e, nullptr, Kb);
    sgemm_kernel<<<ggrid, 256>>>(E, Wv_e, nullptr, Vb);
    flash_kernel<<<fgrid, 256, FS_BYTES>>>(Qb, Kb, Vb, Sb);           // sa_e
    ln_add_kernel<<<BSr, 256>>>(Sb, ge, be, E, 1.0f, I);              // inter_e
    sgemm_kernel<<<ggrid, 256>>>(I, Wff_e, E, EO);                    // enc_out = inter@Wff + enc_in

    // ---- Decoder ----
    add_pos_kernel<<<BSD / 256, 256>>>(in1, DI);                      // dec_in
    sgemm_kernel<<<ggrid, 256>>>(DI, Wq_d, nullptr, Qb);
    sgemm_kernel<<<ggrid, 256>>>(DI, Wk_d, nullptr, Kb);
    sgemm_kernel<<<ggrid, 256>>>(DI, Wv_d, nullptr, Vb);
    flash_kernel<<<fgrid, 256, FS_BYTES>>>(Qb, Kb, Vb, Sb);           // sa_d
    ln_add_kernel<<<BSr, 256>>>(Sb, gd, bd, DI, 2.0f, I);             // i2 = dec_in + 2*LN(sa_d)
    flash_kernel<<<fgrid, 256, FS_BYTES>>>(EO, EO, EO, Qb);           // eda (Q=K=V=enc_out)
    sgemm_kernel<<<ggrid, 256>>>(Qb, Wff_d, I, out);                  // dec_out = eda@Wff_d + i2
}